// round 6
// baseline (speedup 1.0000x reference)
#include <cuda_runtime.h>

#define N_NODES 100000
#define NFEAT   64
#define N_EDGES 1600000

#define SCAN_BLK 1024
#define N_SCAN_BLOCKS ((N_NODES + SCAN_BLK - 1) / SCAN_BLK)   // 98

// Device-global scratch (no allocation allowed)
__device__ int g_count[N_NODES];
__device__ int g_off[N_NODES + 1];
__device__ int g_cursor[N_NODES];
__device__ int g_perm[N_EDGES];
__device__ int g_bsum[N_SCAN_BLOCKS];
__device__ int g_bsumx[N_SCAN_BLOCKS];

// ---------------------------------------------------------------------------
// Pass 1: zero counts
// ---------------------------------------------------------------------------
__global__ void k_zero_counts() {
    int i = blockIdx.x * blockDim.x + threadIdx.x;
    if (i < N_NODES) g_count[i] = 0;
}

// ---------------------------------------------------------------------------
// Pass 2: histogram of dst
// ---------------------------------------------------------------------------
__global__ void k_count(const int* __restrict__ ei) {
    int e = blockIdx.x * blockDim.x + threadIdx.x;
    if (e >= N_EDGES) return;
    int d = __ldg(ei + N_EDGES + e);
    if ((unsigned)d < N_NODES) atomicAdd(&g_count[d], 1);
}

// ---------------------------------------------------------------------------
// Pass 3a: per-block exclusive scan of counts (block = 1024)
// ---------------------------------------------------------------------------
__global__ void k_scan1() {
    __shared__ int sdata[SCAN_BLK];
    int tid = threadIdx.x;
    int i = blockIdx.x * SCAN_BLK + tid;
    int v = (i < N_NODES) ? g_count[i] : 0;
    sdata[tid] = v;
    __syncthreads();
    #pragma unroll
    for (int d = 1; d < SCAN_BLK; d <<= 1) {
        int t = (tid >= d) ? sdata[tid - d] : 0;
        __syncthreads();
        sdata[tid] += t;
        __syncthreads();
    }
    if (i < N_NODES) g_off[i] = sdata[tid] - v;          // exclusive
    if (tid == SCAN_BLK - 1) g_bsum[blockIdx.x] = sdata[tid];
}

// ---------------------------------------------------------------------------
// Pass 3b: PARALLEL exclusive scan of the 98 block sums (1 block, 128 thr)
// ---------------------------------------------------------------------------
__global__ void k_scan2p() {
    __shared__ int sd[128];
    int t = threadIdx.x;
    int v = (t < N_SCAN_BLOCKS) ? g_bsum[t] : 0;
    sd[t] = v;
    __syncthreads();
    #pragma unroll
    for (int d = 1; d < 128; d <<= 1) {
        int tv = (t >= d) ? sd[t - d] : 0;
        __syncthreads();
        sd[t] += tv;
        __syncthreads();
    }
    if (t < N_SCAN_BLOCKS) g_bsumx[t] = sd[t] - v;       // exclusive
}

// ---------------------------------------------------------------------------
// Pass 3c: add block offsets; init cursor; seal g_off[N]
// ---------------------------------------------------------------------------
__global__ void k_scan3() {
    int i = blockIdx.x * blockDim.x + threadIdx.x;
    if (i < N_NODES) {
        int off = g_off[i] + g_bsumx[i >> 10];
        g_off[i] = off;
        g_cursor[i] = off;
    }
    if (i == 0) g_off[N_NODES] = N_EDGES;
}

// ---------------------------------------------------------------------------
// Pass 4: fill permutation: perm[pos] = src, grouped by dst
// ---------------------------------------------------------------------------
__global__ void k_fill(const int* __restrict__ ei) {
    int e = blockIdx.x * blockDim.x + threadIdx.x;
    if (e >= N_EDGES) return;
    int s = __ldg(ei + e);
    int d = __ldg(ei + N_EDGES + e);
    if ((unsigned)d >= N_NODES || (unsigned)s >= N_NODES) return;
    int pos = atomicAdd(&g_cursor[d], 1);
    g_perm[pos] = s;
}

// ---------------------------------------------------------------------------
// Pass 5 (FUSED): gather-sum + (1+eps)x + full MLP, persistent tile loop.
// 256 threads / block, 16 nodes per tile. Thread (n_l = t>>4, q = t&15).
//  A: gather float4 chunk q of node n_l's aggregated row -> sh
//  B: hidden units q*4..q*4+3 of node n_l (64->64 GEMM + bias + relu) -> sh2
//  C: output class q of node n_l (64->16 GEMM + bias) -> gmem
// smem pitch 68 floats (16B-aligned, bank-rotating).
// ---------------------------------------------------------------------------
#define FUSED_GRID (148 * 7)

__global__ __launch_bounds__(256) void k_fused(const float4* __restrict__ x4,
                                               const float* __restrict__ eps,
                                               const float* __restrict__ W1,
                                               const float* __restrict__ b1,
                                               const float* __restrict__ W2,
                                               const float* __restrict__ b2,
                                               float* __restrict__ out) {
    __shared__ float sW1[4096];       // [64][64] k-major
    __shared__ float sW2[1024];       // [64][16]
    __shared__ float sb1[64];
    __shared__ float sb2[16];
    __shared__ __align__(16) float sh[16 * 68];   // gathered rows
    __shared__ __align__(16) float sh2[16 * 68];  // hidden rows

    int t = threadIdx.x;
    for (int i = t; i < 4096; i += 256) sW1[i] = W1[i];
    for (int i = t; i < 1024; i += 256) sW2[i] = W2[i];
    if (t < 64) sb1[t] = b1[t];
    if (t < 16) sb2[t] = b2[t];

    float s = 1.0f + __ldg(eps);
    int n_l = t >> 4;       // node within tile: 0..15
    int q   = t & 15;       // chunk / hidden-quad / class index
    __syncthreads();

    const int n_tiles = N_NODES / 16;           // 6250, exact
    for (int tile = blockIdx.x; tile < n_tiles; tile += gridDim.x) {
        int node = tile * 16 + n_l;

        // ---- A: gather ----
        float4 a = __ldg(x4 + (size_t)node * 16 + q);
        float4 acc = make_float4(a.x * s, a.y * s, a.z * s, a.w * s);
        int j   = __ldg(&g_off[node]);
        int end = __ldg(&g_off[node + 1]);
        for (; j < end; j++) {
            int src = __ldg(&g_perm[j]);
            float4 v = __ldg(x4 + (size_t)src * 16 + q);
            acc.x += v.x; acc.y += v.y; acc.z += v.z; acc.w += v.w;
        }
        *reinterpret_cast<float4*>(&sh[n_l * 68 + q * 4]) = acc;
        __syncthreads();

        // ---- B: layer 1 (64 -> 64), 4 hidden units per thread ----
        float a0 = sb1[q * 4 + 0], a1 = sb1[q * 4 + 1];
        float a2 = sb1[q * 4 + 2], a3 = sb1[q * 4 + 3];
        #pragma unroll 8
        for (int k = 0; k < 64; k++) {
            float hk = sh[n_l * 68 + k];
            float4 w = *reinterpret_cast<const float4*>(&sW1[k * 64 + q * 4]);
            a0 += hk * w.x; a1 += hk * w.y; a2 += hk * w.z; a3 += hk * w.w;
        }
        float4 hr = make_float4(fmaxf(a0, 0.0f), fmaxf(a1, 0.0f),
                                fmaxf(a2, 0.0f), fmaxf(a3, 0.0f));
        *reinterpret_cast<float4*>(&sh2[n_l * 68 + q * 4]) = hr;
        __syncthreads();

        // ---- C: layer 2 (64 -> 16), 1 class per thread ----
        float o = sb2[q];
        #pragma unroll 8
        for (int k = 0; k < 64; k++) {
            o += sh2[n_l * 68 + k] * sW2[k * 16 + q];
        }
        out[(size_t)node * 16 + q] = o;
        __syncthreads();
    }
}

// ---------------------------------------------------------------------------
extern "C" void kernel_launch(void* const* d_in, const int* in_sizes, int n_in,
                              void* d_out, int out_size) {
    const float* x   = (const float*)d_in[0];
    const int*   ei  = (const int*)d_in[1];   // int64 downcast to int32 by harness
    const float* eps = (const float*)d_in[2];
    const float* W1  = (const float*)d_in[3];
    const float* b1  = (const float*)d_in[4];
    const float* W2  = (const float*)d_in[5];
    const float* b2  = (const float*)d_in[6];
    float*       out = (float*)d_out;

    const int EB = (N_EDGES + 255) / 256;
    const int NB = (N_NODES + 255) / 256;

    k_zero_counts<<<NB, 256>>>();
    k_count<<<EB, 256>>>(ei);
    k_scan1<<<N_SCAN_BLOCKS, SCAN_BLK>>>();
    k_scan2p<<<1, 128>>>();
    k_scan3<<<NB, 256>>>();
    k_fill<<<EB, 256>>>(ei);
    k_fused<<<FUSED_GRID, 256>>>((const float4*)x, eps, W1, b1, W2, b2, out);
}

// round 7
// speedup vs baseline: 1.1758x; 1.1758x over previous
#include <cuda_runtime.h>

#define N_NODES 100000
#define NFEAT   64
#define N_EDGES 1600000

#define SCAN_BLK 1024
#define N_SCAN_BLOCKS ((N_NODES + SCAN_BLK - 1) / SCAN_BLK)   // 98

// Device-global scratch (no allocation allowed)
__device__ __align__(16) float g_agg[N_NODES * NFEAT];
__device__ int g_count[N_NODES];
__device__ int g_off[N_NODES + 1];
__device__ int g_cursor[N_NODES];
__device__ int g_perm[N_EDGES];
__device__ int g_bsum[N_SCAN_BLOCKS];
__device__ int g_bsumx[N_SCAN_BLOCKS];

// ---------------------------------------------------------------------------
// Pass 1: zero counts
// ---------------------------------------------------------------------------
__global__ void k_zero_counts() {
    int i = blockIdx.x * blockDim.x + threadIdx.x;
    if (i < N_NODES) g_count[i] = 0;
}

// ---------------------------------------------------------------------------
// Pass 2: histogram of dst
// ---------------------------------------------------------------------------
__global__ void k_count(const int* __restrict__ ei) {
    int e = blockIdx.x * blockDim.x + threadIdx.x;
    if (e >= N_EDGES) return;
    int d = __ldg(ei + N_EDGES + e);
    if ((unsigned)d < N_NODES) atomicAdd(&g_count[d], 1);
}

// ---------------------------------------------------------------------------
// Pass 3a: per-block exclusive scan of counts (block = 1024)
// ---------------------------------------------------------------------------
__global__ void k_scan1() {
    __shared__ int sdata[SCAN_BLK];
    int tid = threadIdx.x;
    int i = blockIdx.x * SCAN_BLK + tid;
    int v = (i < N_NODES) ? g_count[i] : 0;
    sdata[tid] = v;
    __syncthreads();
    #pragma unroll
    for (int d = 1; d < SCAN_BLK; d <<= 1) {
        int t = (tid >= d) ? sdata[tid - d] : 0;
        __syncthreads();
        sdata[tid] += t;
        __syncthreads();
    }
    if (i < N_NODES) g_off[i] = sdata[tid] - v;          // exclusive
    if (tid == SCAN_BLK - 1) g_bsum[blockIdx.x] = sdata[tid];
}

// ---------------------------------------------------------------------------
// Pass 3b: PARALLEL exclusive scan of the 98 block sums (1 block, 128 thr)
// ---------------------------------------------------------------------------
__global__ void k_scan2p() {
    __shared__ int sd[128];
    int t = threadIdx.x;
    int v = (t < N_SCAN_BLOCKS) ? g_bsum[t] : 0;
    sd[t] = v;
    __syncthreads();
    #pragma unroll
    for (int d = 1; d < 128; d <<= 1) {
        int tv = (t >= d) ? sd[t - d] : 0;
        __syncthreads();
        sd[t] += tv;
        __syncthreads();
    }
    if (t < N_SCAN_BLOCKS) g_bsumx[t] = sd[t] - v;       // exclusive
}

// ---------------------------------------------------------------------------
// Pass 3c: add block offsets; init cursor; seal g_off[N]
// ---------------------------------------------------------------------------
__global__ void k_scan3() {
    int i = blockIdx.x * blockDim.x + threadIdx.x;
    if (i < N_NODES) {
        int off = g_off[i] + g_bsumx[i >> 10];
        g_off[i] = off;
        g_cursor[i] = off;
    }
    if (i == 0) g_off[N_NODES] = N_EDGES;
}

// ---------------------------------------------------------------------------
// Pass 4: fill permutation: perm[pos] = src, grouped by dst
// ---------------------------------------------------------------------------
__global__ void k_fill(const int* __restrict__ ei) {
    int e = blockIdx.x * blockDim.x + threadIdx.x;
    if (e >= N_EDGES) return;
    int s = __ldg(ei + e);
    int d = __ldg(ei + N_EDGES + e);
    if ((unsigned)d >= N_NODES || (unsigned)s >= N_NODES) return;
    int pos = atomicAdd(&g_cursor[d], 1);
    g_perm[pos] = s;
}

// ---------------------------------------------------------------------------
// Pass 5: segment gather-sum + (1+eps)*x fold-in. 16 threads per node,
// thread q owns float4 chunk q. Edge loop unrolled x2 (2 loads in flight).
// ---------------------------------------------------------------------------
__global__ void k_gather(const float4* __restrict__ x4,
                         const float* __restrict__ eps) {
    int tid = blockIdx.x * blockDim.x + threadIdx.x;
    int node = tid >> 4;
    int q = tid & 15;
    if (node >= N_NODES) return;

    float s = 1.0f + __ldg(eps);
    float4 a = __ldg(x4 + (size_t)node * 16 + q);
    float4 acc0 = make_float4(a.x * s, a.y * s, a.z * s, a.w * s);
    float4 acc1 = make_float4(0.0f, 0.0f, 0.0f, 0.0f);

    int j   = __ldg(&g_off[node]);
    int end = __ldg(&g_off[node + 1]);
    for (; j + 1 < end; j += 2) {
        int s0 = __ldg(&g_perm[j]);
        int s1 = __ldg(&g_perm[j + 1]);
        float4 v0 = __ldg(x4 + (size_t)s0 * 16 + q);
        float4 v1 = __ldg(x4 + (size_t)s1 * 16 + q);
        acc0.x += v0.x; acc0.y += v0.y; acc0.z += v0.z; acc0.w += v0.w;
        acc1.x += v1.x; acc1.y += v1.y; acc1.z += v1.z; acc1.w += v1.w;
    }
    if (j < end) {
        int s0 = __ldg(&g_perm[j]);
        float4 v0 = __ldg(x4 + (size_t)s0 * 16 + q);
        acc0.x += v0.x; acc0.y += v0.y; acc0.z += v0.z; acc0.w += v0.w;
    }
    acc0.x += acc1.x; acc0.y += acc1.y; acc0.z += acc1.z; acc0.w += acc1.w;
    reinterpret_cast<float4*>(g_agg)[(size_t)node * 16 + q] = acc0;
}

// ---------------------------------------------------------------------------
// Pass 6: out = relu(agg @ W1 + b1) @ W2 + b2   (fully fused per node)
// 128 threads/block, one node per thread. Weights + node tile staged in smem.
// ---------------------------------------------------------------------------
extern __shared__ float smem[];

__global__ void gin_mlp_kernel(const float* __restrict__ W1,
                               const float* __restrict__ b1,
                               const float* __restrict__ W2,
                               const float* __restrict__ b2,
                               float* __restrict__ out) {
    float* sW1 = smem;            // [64][64]
    float* sW2 = smem + 4096;     // [64][16]
    float* sb1 = smem + 5120;     // [64]
    float* sb2 = smem + 5184;     // [16]
    float* sh  = smem + 5200;     // [128][65]

    int t = threadIdx.x;

    for (int i = t; i < 4096; i += 128) sW1[i] = W1[i];
    for (int i = t; i < 1024; i += 128) sW2[i] = W2[i];
    if (t < 64) sb1[t] = b1[t];
    if (t < 16) sb2[t] = b2[t];

    int node0 = blockIdx.x * 128;
    int nrows = N_NODES - node0; if (nrows > 128) nrows = 128;

    for (int i = t; i < nrows * 64; i += 128) {
        sh[(i >> 6) * 65 + (i & 63)] = g_agg[(size_t)node0 * 64 + i];
    }
    __syncthreads();

    int node = node0 + t;
    if (node >= N_NODES) return;

    const float* h = sh + t * 65;

    float o[16];
    #pragma unroll
    for (int c = 0; c < 16; c++) o[c] = sb2[c];

    for (int jc = 0; jc < 4; jc++) {
        float acc[16];
        #pragma unroll
        for (int u = 0; u < 16; u++) acc[u] = sb1[jc * 16 + u];

        #pragma unroll 8
        for (int k = 0; k < 64; k++) {
            float hk = h[k];
            const float4* wr = reinterpret_cast<const float4*>(sW1 + k * 64 + jc * 16);
            float4 w0 = wr[0], w1 = wr[1], w2 = wr[2], w3 = wr[3];
            acc[ 0] += hk * w0.x; acc[ 1] += hk * w0.y; acc[ 2] += hk * w0.z; acc[ 3] += hk * w0.w;
            acc[ 4] += hk * w1.x; acc[ 5] += hk * w1.y; acc[ 6] += hk * w1.z; acc[ 7] += hk * w1.w;
            acc[ 8] += hk * w2.x; acc[ 9] += hk * w2.y; acc[10] += hk * w2.z; acc[11] += hk * w2.w;
            acc[12] += hk * w3.x; acc[13] += hk * w3.y; acc[14] += hk * w3.z; acc[15] += hk * w3.w;
        }

        #pragma unroll
        for (int u = 0; u < 16; u++) {
            float hr = fmaxf(acc[u], 0.0f);
            const float4* w2r = reinterpret_cast<const float4*>(sW2 + (jc * 16 + u) * 16);
            float4 a = w2r[0], b = w2r[1], c = w2r[2], d = w2r[3];
            o[ 0] += hr * a.x; o[ 1] += hr * a.y; o[ 2] += hr * a.z; o[ 3] += hr * a.w;
            o[ 4] += hr * b.x; o[ 5] += hr * b.y; o[ 6] += hr * b.z; o[ 7] += hr * b.w;
            o[ 8] += hr * c.x; o[ 9] += hr * c.y; o[10] += hr * c.z; o[11] += hr * c.w;
            o[12] += hr * d.x; o[13] += hr * d.y; o[14] += hr * d.z; o[15] += hr * d.w;
        }
    }

    float4* op = reinterpret_cast<float4*>(out + (size_t)node * 16);
    op[0] = make_float4(o[ 0], o[ 1], o[ 2], o[ 3]);
    op[1] = make_float4(o[ 4], o[ 5], o[ 6], o[ 7]);
    op[2] = make_float4(o[ 8], o[ 9], o[10], o[11]);
    op[3] = make_float4(o[12], o[13], o[14], o[15]);
}

// ---------------------------------------------------------------------------
extern "C" void kernel_launch(void* const* d_in, const int* in_sizes, int n_in,
                              void* d_out, int out_size) {
    const float* x   = (const float*)d_in[0];
    const int*   ei  = (const int*)d_in[1];   // int64 downcast to int32 by harness
    const float* eps = (const float*)d_in[2];
    const float* W1  = (const float*)d_in[3];
    const float* b1  = (const float*)d_in[4];
    const float* W2  = (const float*)d_in[5];
    const float* b2  = (const float*)d_in[6];
    float*       out = (float*)d_out;

    const int EB = (N_EDGES + 255) / 256;
    const int NB = (N_NODES + 255) / 256;

    k_zero_counts<<<NB, 256>>>();
    k_count<<<EB, 256>>>(ei);
    k_scan1<<<N_SCAN_BLOCKS, SCAN_BLK>>>();
    k_scan2p<<<1, 128>>>();
    k_scan3<<<NB, 256>>>();
    k_fill<<<EB, 256>>>(ei);

    {
        long long total = (long long)N_NODES * 16;
        int blocks = (int)((total + 255) / 256);
        k_gather<<<blocks, 256>>>((const float4*)x, eps);
    }

    {
        size_t shbytes = (size_t)(4096 + 1024 + 64 + 16 + 128 * 65) * sizeof(float);
        cudaFuncSetAttribute(gin_mlp_kernel,
                             cudaFuncAttributeMaxDynamicSharedMemorySize,
                             (int)shbytes);
        int blocks = (N_NODES + 127) / 128;
        gin_mlp_kernel<<<blocks, 128, shbytes>>>(W1, b1, W2, b2, out);
    }
}

// round 10
// speedup vs baseline: 1.6621x; 1.4136x over previous
#include <cuda_runtime.h>
#include <cstdint>

#define N_NODES 100000
#define N_EDGES 1600000

#define SCAN_BLK 1024
#define N_SCAN_BLOCKS ((N_NODES + SCAN_BLK - 1) / SCAN_BLK)   // 98

// Device-global scratch (no allocation allowed).
// g_count is zero-initialized at module load and re-zeroed by k_scan1 after
// use, so every kernel_launch call sees zeros (deterministic, same work).
__device__ __align__(16) float g_agg[N_NODES * 64];
__device__ int g_count[N_NODES];
__device__ int g_off[N_NODES + 1];
__device__ int g_cursor[N_NODES];
__device__ int g_perm[N_EDGES];
__device__ int g_bsum[N_SCAN_BLOCKS];
__device__ int g_bsumx[N_SCAN_BLOCKS];

// ---------------------------------------------------------------------------
// Pass 1: histogram of dst (counts are zero on entry)
// ---------------------------------------------------------------------------
__global__ void k_count(const int* __restrict__ ei) {
    int e = blockIdx.x * blockDim.x + threadIdx.x;
    if (e >= N_EDGES) return;
    int d = __ldg(ei + N_EDGES + e);
    if ((unsigned)d < N_NODES) atomicAdd(&g_count[d], 1);
}

// ---------------------------------------------------------------------------
// Pass 2a: per-block exclusive scan of counts; self-cleans g_count to zero
// ---------------------------------------------------------------------------
__global__ void k_scan1() {
    __shared__ int sdata[SCAN_BLK];
    int tid = threadIdx.x;
    int i = blockIdx.x * SCAN_BLK + tid;
    int v = (i < N_NODES) ? g_count[i] : 0;
    sdata[tid] = v;
    __syncthreads();
    #pragma unroll
    for (int d = 1; d < SCAN_BLK; d <<= 1) {
        int t = (tid >= d) ? sdata[tid - d] : 0;
        __syncthreads();
        sdata[tid] += t;
        __syncthreads();
    }
    if (i < N_NODES) {
        g_off[i] = sdata[tid] - v;          // exclusive
        g_count[i] = 0;                     // clean for next call
    }
    if (tid == SCAN_BLK - 1) g_bsum[blockIdx.x] = sdata[tid];
}

// ---------------------------------------------------------------------------
// Pass 2b: parallel exclusive scan of the 98 block sums
// ---------------------------------------------------------------------------
__global__ void k_scan2p() {
    __shared__ int sd[128];
    int t = threadIdx.x;
    int v = (t < N_SCAN_BLOCKS) ? g_bsum[t] : 0;
    sd[t] = v;
    __syncthreads();
    #pragma unroll
    for (int d = 1; d < 128; d <<= 1) {
        int tv = (t >= d) ? sd[t - d] : 0;
        __syncthreads();
        sd[t] += tv;
        __syncthreads();
    }
    if (t < N_SCAN_BLOCKS) g_bsumx[t] = sd[t] - v;       // exclusive
}

// ---------------------------------------------------------------------------
// Pass 2c: add block offsets; init cursor; seal g_off[N]
// ---------------------------------------------------------------------------
__global__ void k_scan3() {
    int i = blockIdx.x * blockDim.x + threadIdx.x;
    if (i < N_NODES) {
        int off = g_off[i] + g_bsumx[i >> 10];
        g_off[i] = off;
        g_cursor[i] = off;
    }
    if (i == 0) g_off[N_NODES] = N_EDGES;
}

// ---------------------------------------------------------------------------
// Pass 3: fill permutation: perm[pos] = src, grouped by dst
// ---------------------------------------------------------------------------
__global__ void k_fill(const int* __restrict__ ei) {
    int e = blockIdx.x * blockDim.x + threadIdx.x;
    if (e >= N_EDGES) return;
    int s = __ldg(ei + e);
    int d = __ldg(ei + N_EDGES + e);
    if ((unsigned)d >= N_NODES || (unsigned)s >= N_NODES) return;
    int pos = atomicAdd(&g_cursor[d], 1);
    g_perm[pos] = s;
}

// ---------------------------------------------------------------------------
// Pass 4: segment gather-sum + (1+eps)*x fold-in. 16 threads/node, float4.
// ---------------------------------------------------------------------------
__global__ void k_gather(const float4* __restrict__ x4,
                         const float* __restrict__ eps) {
    int tid = blockIdx.x * blockDim.x + threadIdx.x;
    int node = tid >> 4;
    int q = tid & 15;
    if (node >= N_NODES) return;

    float s = 1.0f + __ldg(eps);
    float4 a = __ldg(x4 + (size_t)node * 16 + q);
    float4 acc0 = make_float4(a.x * s, a.y * s, a.z * s, a.w * s);
    float4 acc1 = make_float4(0.0f, 0.0f, 0.0f, 0.0f);

    int j   = __ldg(&g_off[node]);
    int end = __ldg(&g_off[node + 1]);
    for (; j + 1 < end; j += 2) {
        int s0 = __ldg(&g_perm[j]);
        int s1 = __ldg(&g_perm[j + 1]);
        float4 v0 = __ldg(x4 + (size_t)s0 * 16 + q);
        float4 v1 = __ldg(x4 + (size_t)s1 * 16 + q);
        acc0.x += v0.x; acc0.y += v0.y; acc0.z += v0.z; acc0.w += v0.w;
        acc1.x += v1.x; acc1.y += v1.y; acc1.z += v1.z; acc1.w += v1.w;
    }
    if (j < end) {
        int s0 = __ldg(&g_perm[j]);
        float4 v0 = __ldg(x4 + (size_t)s0 * 16 + q);
        acc0.x += v0.x; acc0.y += v0.y; acc0.z += v0.z; acc0.w += v0.w;
    }
    acc0.x += acc1.x; acc0.y += acc1.y; acc0.z += acc1.z; acc0.w += acc1.w;
    reinterpret_cast<float4*>(g_agg)[(size_t)node * 16 + q] = acc0;
}

// ---------------------------------------------------------------------------
// Pass 5: out = relu(agg @ W1 + b1) @ W2 + b2 via tf32 mma.sync.m16n8k8.
// 128 threads = 4 warps; 64-node tile; warp w owns rows w*16..w*16+15.
// Weights pre-swizzled to fragment order in smem (lane-indexed, conflict-free).
// A-fragments (and H-fragments) loaded once into regs, reused across n-tiles.
// ---------------------------------------------------------------------------
#define N_TILES ((N_NODES + 63) / 64)      // 1563
#define MLP_GRID (148 * 4)

__device__ __forceinline__ uint32_t f2tf32(float v) {
    uint32_t r;
    asm("cvt.rna.tf32.f32 %0, %1;" : "=r"(r) : "f"(v));
    return r;
}

__device__ __forceinline__ void mma_tf32(float& c0, float& c1, float& c2, float& c3,
                                         uint32_t a0, uint32_t a1, uint32_t a2, uint32_t a3,
                                         uint32_t b0, uint32_t b1) {
    asm volatile(
        "mma.sync.aligned.m16n8k8.row.col.f32.tf32.tf32.f32 "
        "{%0,%1,%2,%3}, {%4,%5,%6,%7}, {%8,%9}, {%0,%1,%2,%3};"
        : "+f"(c0), "+f"(c1), "+f"(c2), "+f"(c3)
        : "r"(a0), "r"(a1), "r"(a2), "r"(a3), "r"(b0), "r"(b1));
}

extern __shared__ float smlp[];

__global__ __launch_bounds__(128) void k_mlp_tc(const float* __restrict__ W1,
                                                const float* __restrict__ b1,
                                                const float* __restrict__ W2,
                                                const float* __restrict__ b2,
                                                float* __restrict__ out) {
    uint32_t* sA   = (uint32_t*)smlp;              // [64][68] tf32 bits
    uint32_t* sH   = sA + 64 * 68;                 // [64][68] tf32 bits
    uint32_t* sW1B = sH + 64 * 68;                 // [8nt][8k][2][32] = 4096
    uint32_t* sW2B = sW1B + 4096;                  // [2nt][8k][2][32] = 1024
    float*    sb1  = (float*)(sW2B + 1024);        // [64]
    float*    sb2  = sb1 + 64;                     // [16]

    int t = threadIdx.x;
    int lane = t & 31, w = t >> 5;
    int g = lane >> 2, tig = lane & 3;

    // Pre-swizzle weights to fragment order (tf32). b0 half=0, b1 half=1.
    for (int i = t; i < 4096; i += 128) {
        int l = i & 31, half = (i >> 5) & 1, kk = (i >> 6) & 7, nt = i >> 9;
        int gg = l >> 2, tt = l & 3;
        sW1B[i] = f2tf32(W1[(kk * 8 + tt + half * 4) * 64 + nt * 8 + gg]);
    }
    for (int i = t; i < 1024; i += 128) {
        int l = i & 31, half = (i >> 5) & 1, kk = (i >> 6) & 7, nt = i >> 9;
        int gg = l >> 2, tt = l & 3;
        sW2B[i] = f2tf32(W2[(kk * 8 + tt + half * 4) * 16 + nt * 8 + gg]);
    }
    if (t < 64) sb1[t] = b1[t];
    if (t < 16) sb2[t] = b2[t];

    for (int tile = blockIdx.x; tile < N_TILES; tile += gridDim.x) {
        int node0 = tile * 64;
        int nrows = N_NODES - node0; if (nrows > 64) nrows = 64;

        __syncthreads();   // weights ready (1st iter) / prior readers done
        // Stage agg tile as tf32 bits, zero-pad missing rows
        for (int i = t; i < 1024; i += 128) {
            int r = i >> 4, c4 = (i & 15) * 4;
            float4 v = (r < nrows)
                ? *reinterpret_cast<const float4*>(&g_agg[(size_t)(node0 + r) * 64 + c4])
                : make_float4(0.f, 0.f, 0.f, 0.f);
            uint32_t* dst = &sA[r * 68 + c4];
            dst[0] = f2tf32(v.x); dst[1] = f2tf32(v.y);
            dst[2] = f2tf32(v.z); dst[3] = f2tf32(v.w);
        }
        __syncthreads();

        // Load A-fragments once (8 k-steps x 4 regs), reuse across 8 n-tiles
        uint32_t af[32];
        #pragma unroll
        for (int k = 0; k < 8; k++) {
            int row0 = (w * 16 + g) * 68, row1 = (w * 16 + g + 8) * 68;
            af[k * 4 + 0] = sA[row0 + k * 8 + tig];
            af[k * 4 + 1] = sA[row1 + k * 8 + tig];
            af[k * 4 + 2] = sA[row0 + k * 8 + tig + 4];
            af[k * 4 + 3] = sA[row1 + k * 8 + tig + 4];
        }

        // Layer 1: 64 -> 64, relu, H to warp-private smem rows (tf32)
        #pragma unroll
        for (int nt = 0; nt < 8; nt++) {
            float c0 = sb1[nt * 8 + 2 * tig], c1 = sb1[nt * 8 + 2 * tig + 1];
            float c2 = c0, c3 = c1;
            #pragma unroll
            for (int k = 0; k < 8; k++) {
                uint32_t b0 = sW1B[(nt * 8 + k) * 64 + lane];
                uint32_t b1r = sW1B[(nt * 8 + k) * 64 + 32 + lane];
                mma_tf32(c0, c1, c2, c3,
                         af[k * 4 + 0], af[k * 4 + 1], af[k * 4 + 2], af[k * 4 + 3],
                         b0, b1r);
            }
            int row0 = (w * 16 + g) * 68, row1 = (w * 16 + g + 8) * 68;
            sH[row0 + nt * 8 + 2 * tig]     = f2tf32(fmaxf(c0, 0.0f));
            sH[row0 + nt * 8 + 2 * tig + 1] = f2tf32(fmaxf(c1, 0.0f));
            sH[row1 + nt * 8 + 2 * tig]     = f2tf32(fmaxf(c2, 0.0f));
            sH[row1 + nt * 8 + 2 * tig + 1] = f2tf32(fmaxf(c3, 0.0f));
        }
        __syncwarp();   // H rows are warp-private; cross-lane visibility only

        // Load H-fragments once, reuse across 2 n-tiles
        uint32_t hf[32];
        #pragma unroll
        for (int k = 0; k < 8; k++) {
            int row0 = (w * 16 + g) * 68, row1 = (w * 16 + g + 8) * 68;
            hf[k * 4 + 0] = sH[row0 + k * 8 + tig];
            hf[k * 4 + 1] = sH[row1 + k * 8 + tig];
            hf[k * 4 + 2] = sH[row0 + k * 8 + tig + 4];
            hf[k * 4 + 3] = sH[row1 + k * 8 + tig + 4];
        }

        // Layer 2: 64 -> 16, direct gmem store (float2 per row-half)
        #pragma unroll
        for (int nt = 0; nt < 2; nt++) {
            float c0 = sb2[nt * 8 + 2 * tig], c1 = sb2[nt * 8 + 2 * tig + 1];
            float c2 = c0, c3 = c1;
            #pragma unroll
            for (int k = 0; k < 8; k++) {
                uint32_t b0 = sW2B[(nt * 8 + k) * 64 + lane];
                uint32_t b1r = sW2B[(nt * 8 + k) * 64 + 32 + lane];
                mma_tf32(c0, c1, c2, c3,
                         hf[k * 4 + 0], hf[k * 4 + 1], hf[k * 4 + 2], hf[k * 4 + 3],
                         b0, b1r);
            }
            int col = nt * 8 + 2 * tig;
            int r0 = node0 + w * 16 + g;
            int r2 = r0 + 8;
            if (r0 < N_NODES)
                *reinterpret_cast<float2*>(&out[(size_t)r0 * 16 + col]) = make_float2(c0, c1);
            if (r2 < N_NODES)
                *reinterpret_cast<float2*>(&out[(size_t)r2 * 16 + col]) = make_float2(c2, c3);
        }
    }
}

// ---------------------------------------------------------------------------
extern "C" void kernel_launch(void* const* d_in, const int* in_sizes, int n_in,
                              void* d_out, int out_size) {
    const float* x   = (const float*)d_in[0];
    const int*   ei  = (const int*)d_in[1];   // int64 downcast to int32 by harness
    const float* eps = (const float*)d_in[2];
    const float* W1  = (const float*)d_in[3];
    const float* b1  = (const float*)d_in[4];
    const float* W2  = (const float*)d_in[5];
    const float* b2  = (const float*)d_in[6];
    float*       out = (float*)d_out;

    const int EB = (N_EDGES + 255) / 256;
    const int NB = (N_NODES + 255) / 256;

    k_count<<<EB, 256>>>(ei);
    k_scan1<<<N_SCAN_BLOCKS, SCAN_BLK>>>();
    k_scan2p<<<1, 128>>>();
    k_scan3<<<NB, 256>>>();
    k_fill<<<EB, 256>>>(ei);

    {
        long long total = (long long)N_NODES * 16;
        int blocks = (int)((total + 255) / 256);
        k_gather<<<blocks, 256>>>((const float4*)x, eps);
    }

    {
        size_t shbytes = (size_t)(64 * 68 * 2 + 4096 + 1024) * 4 + (64 + 16) * 4;
        cudaFuncSetAttribute(k_mlp_tc,
                             cudaFuncAttributeMaxDynamicSharedMemorySize,
                             (int)shbytes);
        k_mlp_tc<<<MLP_GRID, 128, shbytes>>>(W1, b1, W2, b2, out);
    }
}

// round 12
// speedup vs baseline: 1.7565x; 1.0568x over previous
#include <cuda_runtime.h>
#include <cuda_fp16.h>
#include <cstdint>

#define N_NODES 100000
#define N_EDGES 1600000

#define SCAN_BLK 1024
#define N_SCAN_BLOCKS ((N_NODES + SCAN_BLK - 1) / SCAN_BLK)   // 98

#define FLAG_AGG (1ULL << 62)
#define FLAG_INC (2ULL << 62)

// Device-global scratch (no allocation allowed).
// g_count zero-initialized at load; re-zeroed by the scan after each use.
// g_pkt reset by k_count_conv each call (stream-ordered before the scan).
__device__ __align__(16) float  g_agg[N_NODES * 64];
__device__ __align__(16) __half g_xh[N_NODES * 64];
__device__ int g_count[N_NODES];
__device__ int g_off[N_NODES + 1];
__device__ int g_cursor[N_NODES];
__device__ int g_perm[N_EDGES];
__device__ unsigned long long g_pkt[N_SCAN_BLOCKS];

// ---------------------------------------------------------------------------
// Pass 1 (merged): dst histogram + x -> fp16 conversion + scan-state reset.
// N_EDGES == N_NODES*16, so one 1.6M-thread grid covers both jobs exactly.
// ---------------------------------------------------------------------------
__global__ void k_count_conv(const int* __restrict__ ei,
                             const float4* __restrict__ x4) {
    int e = blockIdx.x * blockDim.x + threadIdx.x;
    if (blockIdx.x == 0 && threadIdx.x < N_SCAN_BLOCKS) g_pkt[threadIdx.x] = 0;
    if (e >= N_EDGES) return;

    // x conversion: float4 -> 4 halves (8B store)
    float4 v = __ldg(x4 + e);
    __half2 h0 = __floats2half2_rn(v.x, v.y);
    __half2 h1 = __floats2half2_rn(v.z, v.w);
    uint2 pk;
    pk.x = *reinterpret_cast<uint32_t*>(&h0);
    pk.y = *reinterpret_cast<uint32_t*>(&h1);
    reinterpret_cast<uint2*>(g_xh)[e] = pk;

    // histogram
    int d = __ldg(ei + N_EDGES + e);
    if ((unsigned)d < N_NODES) atomicAdd(&g_count[d], 1);
}

// ---------------------------------------------------------------------------
// Pass 2: single-pass exclusive scan with decoupled lookback.
// 98 blocks x 1024 threads, all co-resident (98 < 148 SMs). Also writes
// g_cursor, seals g_off[N_NODES], and self-cleans g_count.
// ---------------------------------------------------------------------------
__global__ __launch_bounds__(SCAN_BLK) void k_scan_lb() {
    __shared__ int sdata[SCAN_BLK];
    __shared__ int s_exc;
    int tid = threadIdx.x, b = blockIdx.x;
    int i = b * SCAN_BLK + tid;
    int v = (i < N_NODES) ? g_count[i] : 0;
    sdata[tid] = v;
    __syncthreads();
    #pragma unroll
    for (int d = 1; d < SCAN_BLK; d <<= 1) {
        int t = (tid >= d) ? sdata[tid - d] : 0;
        __syncthreads();
        sdata[tid] += t;
        __syncthreads();
    }
    int incl = sdata[tid];
    int total = sdata[SCAN_BLK - 1];

    if (b == 0) {
        if (tid == 0) {
            s_exc = 0;
            atomicExch(&g_pkt[0], FLAG_INC | (unsigned long long)(unsigned)total);
        }
    } else {
        if (tid == 0)
            atomicExch(&g_pkt[b], FLAG_AGG | (unsigned long long)(unsigned)total);
        if (tid < 32) {
            int exc = 0;
            int look = b - 1;
            while (true) {
                int idx = look - 31 + tid;           // lane 31 reads 'look'
                unsigned long long p = 0;
                if (idx >= 0) {
                    do { p = atomicAdd(&g_pkt[idx], 0ULL); } while (p < FLAG_AGG);
                }
                int myval = (idx >= 0) ? (int)(p & 0xFFFFFFFFULL) : 0;
                unsigned incmask = __ballot_sync(0xFFFFFFFFu,
                                                 idx >= 0 && (p & FLAG_INC));
                if (incmask) {
                    int hi = 31 - __clz(incmask);    // closest INC predecessor
                    int c = (tid >= hi) ? myval : 0;
                    #pragma unroll
                    for (int o = 16; o; o >>= 1) c += __shfl_xor_sync(0xFFFFFFFFu, c, o);
                    exc += c;
                    break;
                } else {
                    int c = myval;
                    #pragma unroll
                    for (int o = 16; o; o >>= 1) c += __shfl_xor_sync(0xFFFFFFFFu, c, o);
                    exc += c;
                    look -= 32;
                }
            }
            if (tid == 0) {
                s_exc = exc;
                atomicExch(&g_pkt[b],
                           FLAG_INC | (unsigned long long)(unsigned)(exc + total));
            }
        }
    }
    __syncthreads();
    int exc = s_exc;

    if (i < N_NODES) {
        int off = exc + incl - v;    // global exclusive prefix
        g_off[i] = off;
        g_cursor[i] = off;
        g_count[i] = 0;              // clean for next call
    }
    if (b == 0 && tid == 0) g_off[N_NODES] = N_EDGES;
}

// ---------------------------------------------------------------------------
// Pass 3: fill permutation: perm[pos] = src, grouped by dst
// ---------------------------------------------------------------------------
__global__ void k_fill(const int* __restrict__ ei) {
    int e = blockIdx.x * blockDim.x + threadIdx.x;
    if (e >= N_EDGES) return;
    int s = __ldg(ei + e);
    int d = __ldg(ei + N_EDGES + e);
    if ((unsigned)d >= N_NODES || (unsigned)s >= N_NODES) return;
    int pos = atomicAdd(&g_cursor[d], 1);
    g_perm[pos] = s;
}

// ---------------------------------------------------------------------------
// Pass 4: segment gather-sum over fp16 x + fp32 (1+eps)*x self-term.
// 8 threads/node; thread q owns halves [q*8, q*8+8) = one 16B uint4/edge.
// Neighbor traffic halved vs fp32 (205MB through L2). fp32 accumulation.
// ---------------------------------------------------------------------------
__global__ void k_gather_h(const float4* __restrict__ x4,
                           const float* __restrict__ eps) {
    int tid = blockIdx.x * blockDim.x + threadIdx.x;
    int node = tid >> 3;
    int q = tid & 7;
    if (node >= N_NODES) return;

    float s = 1.0f + __ldg(eps);
    float4 a0 = __ldg(x4 + (size_t)node * 16 + q * 2);
    float4 a1 = __ldg(x4 + (size_t)node * 16 + q * 2 + 1);
    float acc0 = a0.x * s, acc1 = a0.y * s, acc2 = a0.z * s, acc3 = a0.w * s;
    float acc4 = a1.x * s, acc5 = a1.y * s, acc6 = a1.z * s, acc7 = a1.w * s;

    int j   = __ldg(&g_off[node]);
    int end = __ldg(&g_off[node + 1]);
    for (; j < end; j++) {
        int src = __ldg(&g_perm[j]);
        uint4 u = *reinterpret_cast<const uint4*>(g_xh + (size_t)src * 64 + q * 8);
        float2 f0 = __half22float2(*reinterpret_cast<__half2*>(&u.x));
        float2 f1 = __half22float2(*reinterpret_cast<__half2*>(&u.y));
        float2 f2 = __half22float2(*reinterpret_cast<__half2*>(&u.z));
        float2 f3 = __half22float2(*reinterpret_cast<__half2*>(&u.w));
        acc0 += f0.x; acc1 += f0.y; acc2 += f1.x; acc3 += f1.y;
        acc4 += f2.x; acc5 += f2.y; acc6 += f3.x; acc7 += f3.y;
    }
    float4* dst = reinterpret_cast<float4*>(g_agg) + (size_t)node * 16 + q * 2;
    dst[0] = make_float4(acc0, acc1, acc2, acc3);
    dst[1] = make_float4(acc4, acc5, acc6, acc7);
}

// ---------------------------------------------------------------------------
// Pass 5: out = relu(agg @ W1 + b1) @ W2 + b2 via tf32 mma.sync.m16n8k8.
// ---------------------------------------------------------------------------
#define N_TILES ((N_NODES + 63) / 64)      // 1563
#define MLP_GRID (148 * 4)

__device__ __forceinline__ uint32_t f2tf32(float v) {
    uint32_t r;
    asm("cvt.rna.tf32.f32 %0, %1;" : "=r"(r) : "f"(v));
    return r;
}

__device__ __forceinline__ void mma_tf32(float& c0, float& c1, float& c2, float& c3,
                                         uint32_t a0, uint32_t a1, uint32_t a2, uint32_t a3,
                                         uint32_t b0, uint32_t b1) {
    asm volatile(
        "mma.sync.aligned.m16n8k8.row.col.f32.tf32.tf32.f32 "
        "{%0,%1,%2,%3}, {%4,%5,%6,%7}, {%8,%9}, {%0,%1,%2,%3};"
        : "+f"(c0), "+f"(c1), "+f"(c2), "+f"(c3)
        : "r"(a0), "r"(a1), "r"(a2), "r"(a3), "r"(b0), "r"(b1));
}

extern __shared__ float smlp[];

__global__ __launch_bounds__(128) void k_mlp_tc(const float* __restrict__ W1,
                                                const float* __restrict__ b1,
                                                const float* __restrict__ W2,
                                                const float* __restrict__ b2,
                                                float* __restrict__ out) {
    uint32_t* sA   = (uint32_t*)smlp;              // [64][68] tf32 bits
    uint32_t* sH   = sA + 64 * 68;                 // [64][68] tf32 bits
    uint32_t* sW1B = sH + 64 * 68;                 // 4096
    uint32_t* sW2B = sW1B + 4096;                  // 1024
    float*    sb1  = (float*)(sW2B + 1024);        // [64]
    float*    sb2  = sb1 + 64;                     // [16]

    int t = threadIdx.x;
    int lane = t & 31, w = t >> 5;
    int g = lane >> 2, tig = lane & 3;

    for (int i = t; i < 4096; i += 128) {
        int l = i & 31, half = (i >> 5) & 1, kk = (i >> 6) & 7, nt = i >> 9;
        int gg = l >> 2, tt = l & 3;
        sW1B[i] = f2tf32(W1[(kk * 8 + tt + half * 4) * 64 + nt * 8 + gg]);
    }
    for (int i = t; i < 1024; i += 128) {
        int l = i & 31, half = (i >> 5) & 1, kk = (i >> 6) & 7, nt = i >> 9;
        int gg = l >> 2, tt = l & 3;
        sW2B[i] = f2tf32(W2[(kk * 8 + tt + half * 4) * 16 + nt * 8 + gg]);
    }
    if (t < 64) sb1[t] = b1[t];
    if (t < 16) sb2[t] = b2[t];

    for (int tile = blockIdx.x; tile < N_TILES; tile += gridDim.x) {
        int node0 = tile * 64;
        int nrows = N_NODES - node0; if (nrows > 64) nrows = 64;

        __syncthreads();
        for (int i = t; i < 1024; i += 128) {
            int r = i >> 4, c4 = (i & 15) * 4;
            float4 v = (r < nrows)
                ? *reinterpret_cast<const float4*>(&g_agg[(size_t)(node0 + r) * 64 + c4])
                : make_float4(0.f, 0.f, 0.f, 0.f);
            uint32_t* dst = &sA[r * 68 + c4];
            dst[0] = f2tf32(v.x); dst[1] = f2tf32(v.y);
            dst[2] = f2tf32(v.z); dst[3] = f2tf32(v.w);
        }
        __syncthreads();

        uint32_t af[32];
        #pragma unroll
        for (int k = 0; k < 8; k++) {
            int row0 = (w * 16 + g) * 68, row1 = (w * 16 + g + 8) * 68;
            af[k * 4 + 0] = sA[row0 + k * 8 + tig];
            af[k * 4 + 1] = sA[row1 + k * 8 + tig];
            af[k * 4 + 2] = sA[row0 + k * 8 + tig + 4];
            af[k * 4 + 3] = sA[row1 + k * 8 + tig + 4];
        }

        #pragma unroll
        for (int nt = 0; nt < 8; nt++) {
            float c0 = sb1[nt * 8 + 2 * tig], c1 = sb1[nt * 8 + 2 * tig + 1];
            float c2 = c0, c3 = c1;
            #pragma unroll
            for (int k = 0; k < 8; k++) {
                uint32_t b0 = sW1B[(nt * 8 + k) * 64 + lane];
                uint32_t b1r = sW1B[(nt * 8 + k) * 64 + 32 + lane];
                mma_tf32(c0, c1, c2, c3,
                         af[k * 4 + 0], af[k * 4 + 1], af[k * 4 + 2], af[k * 4 + 3],
                         b0, b1r);
            }
            int row0 = (w * 16 + g) * 68, row1 = (w * 16 + g + 8) * 68;
            sH[row0 + nt * 8 + 2 * tig]     = f2tf32(fmaxf(c0, 0.0f));
            sH[row0 + nt * 8 + 2 * tig + 1] = f2tf32(fmaxf(c1, 0.0f));
            sH[row1 + nt * 8 + 2 * tig]     = f2tf32(fmaxf(c2, 0.0f));
            sH[row1 + nt * 8 + 2 * tig + 1] = f2tf32(fmaxf(c3, 0.0f));
        }
        __syncwarp();

        uint32_t hf[32];
        #pragma unroll
        for (int k = 0; k < 8; k++) {
            int row0 = (w * 16 + g) * 68, row1 = (w * 16 + g + 8) * 68;
            hf[k * 4 + 0] = sH[row0 + k * 8 + tig];
            hf[k * 4 + 1] = sH[row1 + k * 8 + tig];
            hf[k * 4 + 2] = sH[row0 + k * 8 + tig + 4];
            hf[k * 4 + 3] = sH[row1 + k * 8 + tig + 4];
        }

        #pragma unroll
        for (int nt = 0; nt < 2; nt++) {
            float c0 = sb2[nt * 8 + 2 * tig], c1 = sb2[nt * 8 + 2 * tig + 1];
            float c2 = c0, c3 = c1;
            #pragma unroll
            for (int k = 0; k < 8; k++) {
                uint32_t b0 = sW2B[(nt * 8 + k) * 64 + lane];
                uint32_t b1r = sW2B[(nt * 8 + k) * 64 + 32 + lane];
                mma_tf32(c0, c1, c2, c3,
                         hf[k * 4 + 0], hf[k * 4 + 1], hf[k * 4 + 2], hf[k * 4 + 3],
                         b0, b1r);
            }
            int col = nt * 8 + 2 * tig;
            int r0 = node0 + w * 16 + g;
            int r2 = r0 + 8;
            if (r0 < N_NODES)
                *reinterpret_cast<float2*>(&out[(size_t)r0 * 16 + col]) = make_float2(c0, c1);
            if (r2 < N_NODES)
                *reinterpret_cast<float2*>(&out[(size_t)r2 * 16 + col]) = make_float2(c2, c3);
        }
    }
}

// ---------------------------------------------------------------------------
extern "C" void kernel_launch(void* const* d_in, const int* in_sizes, int n_in,
                              void* d_out, int out_size) {
    const float* x   = (const float*)d_in[0];
    const int*   ei  = (const int*)d_in[1];   // int64 downcast to int32 by harness
    const float* eps = (const float*)d_in[2];
    const float* W1  = (const float*)d_in[3];
    const float* b1  = (const float*)d_in[4];
    const float* W2  = (const float*)d_in[5];
    const float* b2  = (const float*)d_in[6];
    float*       out = (float*)d_out;

    const int EB = (N_EDGES + 255) / 256;     // 6250

    k_count_conv<<<EB, 256>>>(ei, (const float4*)x);
    k_scan_lb<<<N_SCAN_BLOCKS, SCAN_BLK>>>();
    k_fill<<<EB, 256>>>(ei);

    {
        long long total = (long long)N_NODES * 8;
        int blocks = (int)((total + 255) / 256);
        k_gather_h<<<blocks, 256>>>((const float4*)x, eps);
    }

    {
        size_t shbytes = (size_t)(64 * 68 * 2 + 4096 + 1024) * 4 + (64 + 16) * 4;
        cudaFuncSetAttribute(k_mlp_tc,
                             cudaFuncAttributeMaxDynamicSharedMemorySize,
                             (int)shbytes);
        k_mlp_tc<<<MLP_GRID, 128, shbytes>>>(W1, b1, W2, b2, out);
    }
}

// round 13
// speedup vs baseline: 1.7899x; 1.0190x over previous
#include <cuda_runtime.h>
#include <cuda_fp16.h>
#include <cstdint>

#define N_NODES 100000
#define N_EDGES 1600000

#define SCAN_BLK 1024
#define N_SCAN_BLOCKS ((N_NODES + SCAN_BLK - 1) / SCAN_BLK)   // 98

#define FLAG_AGG (1ULL << 62)
#define FLAG_INC (2ULL << 62)

// Device-global scratch (no allocation allowed).
// g_count zero-initialized at load; re-zeroed by the scan after each use.
// g_pkt reset by k_count_conv each call (stream-ordered before the scan).
__device__ __align__(16) float  g_agg[N_NODES * 64];
__device__ __align__(16) __half g_xh[N_NODES * 64];
__device__ int g_count[N_NODES];
__device__ int g_off[N_NODES + 1];
__device__ int g_cursor[N_NODES];
__device__ int g_perm[N_EDGES];
__device__ unsigned long long g_pkt[N_SCAN_BLOCKS];

// ---------------------------------------------------------------------------
// Pass 1 (merged): dst histogram + x -> fp16 conversion + scan-state reset.
// ---------------------------------------------------------------------------
__global__ void k_count_conv(const int* __restrict__ ei,
                             const float4* __restrict__ x4) {
    int e = blockIdx.x * blockDim.x + threadIdx.x;
    if (blockIdx.x == 0 && threadIdx.x < N_SCAN_BLOCKS) g_pkt[threadIdx.x] = 0;
    if (e >= N_EDGES) return;

    float4 v = __ldg(x4 + e);
    __half2 h0 = __floats2half2_rn(v.x, v.y);
    __half2 h1 = __floats2half2_rn(v.z, v.w);
    uint2 pk;
    pk.x = *reinterpret_cast<uint32_t*>(&h0);
    pk.y = *reinterpret_cast<uint32_t*>(&h1);
    reinterpret_cast<uint2*>(g_xh)[e] = pk;

    int d = __ldg(ei + N_EDGES + e);
    if ((unsigned)d < N_NODES) atomicAdd(&g_count[d], 1);
}

// ---------------------------------------------------------------------------
// Pass 2: single-pass exclusive scan with decoupled lookback (98 blocks).
// ---------------------------------------------------------------------------
__global__ __launch_bounds__(SCAN_BLK) void k_scan_lb() {
    __shared__ int sdata[SCAN_BLK];
    __shared__ int s_exc;
    int tid = threadIdx.x, b = blockIdx.x;
    int i = b * SCAN_BLK + tid;
    int v = (i < N_NODES) ? g_count[i] : 0;
    sdata[tid] = v;
    __syncthreads();
    #pragma unroll
    for (int d = 1; d < SCAN_BLK; d <<= 1) {
        int t = (tid >= d) ? sdata[tid - d] : 0;
        __syncthreads();
        sdata[tid] += t;
        __syncthreads();
    }
    int incl = sdata[tid];
    int total = sdata[SCAN_BLK - 1];

    if (b == 0) {
        if (tid == 0) {
            s_exc = 0;
            atomicExch(&g_pkt[0], FLAG_INC | (unsigned long long)(unsigned)total);
        }
    } else {
        if (tid == 0)
            atomicExch(&g_pkt[b], FLAG_AGG | (unsigned long long)(unsigned)total);
        if (tid < 32) {
            int exc = 0;
            int look = b - 1;
            while (true) {
                int idx = look - 31 + tid;           // lane 31 reads 'look'
                unsigned long long p = 0;
                if (idx >= 0) {
                    do { p = atomicAdd(&g_pkt[idx], 0ULL); } while (p < FLAG_AGG);
                }
                int myval = (idx >= 0) ? (int)(p & 0xFFFFFFFFULL) : 0;
                unsigned incmask = __ballot_sync(0xFFFFFFFFu,
                                                 idx >= 0 && (p & FLAG_INC));
                if (incmask) {
                    int hi = 31 - __clz(incmask);    // closest INC predecessor
                    int c = (tid >= hi) ? myval : 0;
                    #pragma unroll
                    for (int o = 16; o; o >>= 1) c += __shfl_xor_sync(0xFFFFFFFFu, c, o);
                    exc += c;
                    break;
                } else {
                    int c = myval;
                    #pragma unroll
                    for (int o = 16; o; o >>= 1) c += __shfl_xor_sync(0xFFFFFFFFu, c, o);
                    exc += c;
                    look -= 32;
                }
            }
            if (tid == 0) {
                s_exc = exc;
                atomicExch(&g_pkt[b],
                           FLAG_INC | (unsigned long long)(unsigned)(exc + total));
            }
        }
    }
    __syncthreads();
    int exc = s_exc;

    if (i < N_NODES) {
        int off = exc + incl - v;
        g_off[i] = off;
        g_cursor[i] = off;
        g_count[i] = 0;
    }
    if (b == 0 && tid == 0) g_off[N_NODES] = N_EDGES;
}

// ---------------------------------------------------------------------------
// Pass 3: fill permutation: perm[pos] = src, grouped by dst
// ---------------------------------------------------------------------------
__global__ void k_fill(const int* __restrict__ ei) {
    int e = blockIdx.x * blockDim.x + threadIdx.x;
    if (e >= N_EDGES) return;
    int s = __ldg(ei + e);
    int d = __ldg(ei + N_EDGES + e);
    if ((unsigned)d >= N_NODES || (unsigned)s >= N_NODES) return;
    int pos = atomicAdd(&g_cursor[d], 1);
    g_perm[pos] = s;
}

// ---------------------------------------------------------------------------
// Pass 4: segment gather-sum over fp16 x + fp32 (1+eps)*x self-term.
// 8 threads/node, thread q owns one 16B chunk. Software-pipelined x4:
// 4 perm reads then 4 independent row loads in flight per iteration.
// ---------------------------------------------------------------------------
__global__ void k_gather_h(const float4* __restrict__ x4,
                           const float* __restrict__ eps) {
    int tid = blockIdx.x * blockDim.x + threadIdx.x;
    int node = tid >> 3;
    int q = tid & 7;
    if (node >= N_NODES) return;

    float s = 1.0f + __ldg(eps);
    float4 a0 = __ldg(x4 + (size_t)node * 16 + q * 2);
    float4 a1 = __ldg(x4 + (size_t)node * 16 + q * 2 + 1);
    float acc0 = a0.x * s, acc1 = a0.y * s, acc2 = a0.z * s, acc3 = a0.w * s;
    float acc4 = a1.x * s, acc5 = a1.y * s, acc6 = a1.z * s, acc7 = a1.w * s;
    float bcc0 = 0.f, bcc1 = 0.f, bcc2 = 0.f, bcc3 = 0.f;
    float bcc4 = 0.f, bcc5 = 0.f, bcc6 = 0.f, bcc7 = 0.f;

    const __half* xh = g_xh;
    int j   = __ldg(&g_off[node]);
    int end = __ldg(&g_off[node + 1]);

    for (; j + 4 <= end; j += 4) {
        int s0 = __ldg(&g_perm[j]);
        int s1 = __ldg(&g_perm[j + 1]);
        int s2 = __ldg(&g_perm[j + 2]);
        int s3 = __ldg(&g_perm[j + 3]);
        uint4 u0 = *reinterpret_cast<const uint4*>(xh + (size_t)s0 * 64 + q * 8);
        uint4 u1 = *reinterpret_cast<const uint4*>(xh + (size_t)s1 * 64 + q * 8);
        uint4 u2 = *reinterpret_cast<const uint4*>(xh + (size_t)s2 * 64 + q * 8);
        uint4 u3 = *reinterpret_cast<const uint4*>(xh + (size_t)s3 * 64 + q * 8);

        float2 f;
        f = __half22float2(*reinterpret_cast<__half2*>(&u0.x)); acc0 += f.x; acc1 += f.y;
        f = __half22float2(*reinterpret_cast<__half2*>(&u0.y)); acc2 += f.x; acc3 += f.y;
        f = __half22float2(*reinterpret_cast<__half2*>(&u0.z)); acc4 += f.x; acc5 += f.y;
        f = __half22float2(*reinterpret_cast<__half2*>(&u0.w)); acc6 += f.x; acc7 += f.y;
        f = __half22float2(*reinterpret_cast<__half2*>(&u1.x)); bcc0 += f.x; bcc1 += f.y;
        f = __half22float2(*reinterpret_cast<__half2*>(&u1.y)); bcc2 += f.x; bcc3 += f.y;
        f = __half22float2(*reinterpret_cast<__half2*>(&u1.z)); bcc4 += f.x; bcc5 += f.y;
        f = __half22float2(*reinterpret_cast<__half2*>(&u1.w)); bcc6 += f.x; bcc7 += f.y;
        f = __half22float2(*reinterpret_cast<__half2*>(&u2.x)); acc0 += f.x; acc1 += f.y;
        f = __half22float2(*reinterpret_cast<__half2*>(&u2.y)); acc2 += f.x; acc3 += f.y;
        f = __half22float2(*reinterpret_cast<__half2*>(&u2.z)); acc4 += f.x; acc5 += f.y;
        f = __half22float2(*reinterpret_cast<__half2*>(&u2.w)); acc6 += f.x; acc7 += f.y;
        f = __half22float2(*reinterpret_cast<__half2*>(&u3.x)); bcc0 += f.x; bcc1 += f.y;
        f = __half22float2(*reinterpret_cast<__half2*>(&u3.y)); bcc2 += f.x; bcc3 += f.y;
        f = __half22float2(*reinterpret_cast<__half2*>(&u3.z)); bcc4 += f.x; bcc5 += f.y;
        f = __half22float2(*reinterpret_cast<__half2*>(&u3.w)); bcc6 += f.x; bcc7 += f.y;
    }
    for (; j < end; j++) {
        int s0 = __ldg(&g_perm[j]);
        uint4 u = *reinterpret_cast<const uint4*>(xh + (size_t)s0 * 64 + q * 8);
        float2 f;
        f = __half22float2(*reinterpret_cast<__half2*>(&u.x)); acc0 += f.x; acc1 += f.y;
        f = __half22float2(*reinterpret_cast<__half2*>(&u.y)); acc2 += f.x; acc3 += f.y;
        f = __half22float2(*reinterpret_cast<__half2*>(&u.z)); acc4 += f.x; acc5 += f.y;
        f = __half22float2(*reinterpret_cast<__half2*>(&u.w)); acc6 += f.x; acc7 += f.y;
    }

    acc0 += bcc0; acc1 += bcc1; acc2 += bcc2; acc3 += bcc3;
    acc4 += bcc4; acc5 += bcc5; acc6 += bcc6; acc7 += bcc7;

    float4* dst = reinterpret_cast<float4*>(g_agg) + (size_t)node * 16 + q * 2;
    dst[0] = make_float4(acc0, acc1, acc2, acc3);
    dst[1] = make_float4(acc4, acc5, acc6, acc7);
}

// ---------------------------------------------------------------------------
// Pass 5: out = relu(agg @ W1 + b1) @ W2 + b2 via tf32 mma.sync.m16n8k8.
// ---------------------------------------------------------------------------
#define N_TILES ((N_NODES + 63) / 64)      // 1563
#define MLP_GRID (148 * 4)

__device__ __forceinline__ uint32_t f2tf32(float v) {
    uint32_t r;
    asm("cvt.rna.tf32.f32 %0, %1;" : "=r"(r) : "f"(v));
    return r;
}

__device__ __forceinline__ void mma_tf32(float& c0, float& c1, float& c2, float& c3,
                                         uint32_t a0, uint32_t a1, uint32_t a2, uint32_t a3,
                                         uint32_t b0, uint32_t b1) {
    asm volatile(
        "mma.sync.aligned.m16n8k8.row.col.f32.tf32.tf32.f32 "
        "{%0,%1,%2,%3}, {%4,%5,%6,%7}, {%8,%9}, {%0,%1,%2,%3};"
        : "+f"(c0), "+f"(c1), "+f"(c2), "+f"(c3)
        : "r"(a0), "r"(a1), "r"(a2), "r"(a3), "r"(b0), "r"(b1));
}

extern __shared__ float smlp[];

__global__ __launch_bounds__(128) void k_mlp_tc(const float* __restrict__ W1,
                                                const float* __restrict__ b1,
                                                const float* __restrict__ W2,
                                                const float* __restrict__ b2,
                                                float* __restrict__ out) {
    uint32_t* sA   = (uint32_t*)smlp;              // [64][68] tf32 bits
    uint32_t* sH   = sA + 64 * 68;                 // [64][68] tf32 bits
    uint32_t* sW1B = sH + 64 * 68;                 // 4096
    uint32_t* sW2B = sW1B + 4096;                  // 1024
    float*    sb1  = (float*)(sW2B + 1024);        // [64]
    float*    sb2  = sb1 + 64;                     // [16]

    int t = threadIdx.x;
    int lane = t & 31, w = t >> 5;
    int g = lane >> 2, tig = lane & 3;

    for (int i = t; i < 4096; i += 128) {
        int l = i & 31, half = (i >> 5) & 1, kk = (i >> 6) & 7, nt = i >> 9;
        int gg = l >> 2, tt = l & 3;
        sW1B[i] = f2tf32(W1[(kk * 8 + tt + half * 4) * 64 + nt * 8 + gg]);
    }
    for (int i = t; i < 1024; i += 128) {
        int l = i & 31, half = (i >> 5) & 1, kk = (i >> 6) & 7, nt = i >> 9;
        int gg = l >> 2, tt = l & 3;
        sW2B[i] = f2tf32(W2[(kk * 8 + tt + half * 4) * 16 + nt * 8 + gg]);
    }
    if (t < 64) sb1[t] = b1[t];
    if (t < 16) sb2[t] = b2[t];

    for (int tile = blockIdx.x; tile < N_TILES; tile += gridDim.x) {
        int node0 = tile * 64;
        int nrows = N_NODES - node0; if (nrows > 64) nrows = 64;

        __syncthreads();
        for (int i = t; i < 1024; i += 128) {
            int r = i >> 4, c4 = (i & 15) * 4;
            float4 v = (r < nrows)
                ? *reinterpret_cast<const float4*>(&g_agg[(size_t)(node0 + r) * 64 + c4])
                : make_float4(0.f, 0.f, 0.f, 0.f);
            uint32_t* dst = &sA[r * 68 + c4];
            dst[0] = f2tf32(v.x); dst[1] = f2tf32(v.y);
            dst[2] = f2tf32(v.z); dst[3] = f2tf32(v.w);
        }
        __syncthreads();

        uint32_t af[32];
        #pragma unroll
        for (int k = 0; k < 8; k++) {
            int row0 = (w * 16 + g) * 68, row1 = (w * 16 + g + 8) * 68;
            af[k * 4 + 0] = sA[row0 + k * 8 + tig];
            af[k * 4 + 1] = sA[row1 + k * 8 + tig];
            af[k * 4 + 2] = sA[row0 + k * 8 + tig + 4];
            af[k * 4 + 3] = sA[row1 + k * 8 + tig + 4];
        }

        #pragma unroll
        for (int nt = 0; nt < 8; nt++) {
            float c0 = sb1[nt * 8 + 2 * tig], c1 = sb1[nt * 8 + 2 * tig + 1];
            float c2 = c0, c3 = c1;
            #pragma unroll
            for (int k = 0; k < 8; k++) {
                uint32_t b0 = sW1B[(nt * 8 + k) * 64 + lane];
                uint32_t b1r = sW1B[(nt * 8 + k) * 64 + 32 + lane];
                mma_tf32(c0, c1, c2, c3,
                         af[k * 4 + 0], af[k * 4 + 1], af[k * 4 + 2], af[k * 4 + 3],
                         b0, b1r);
            }
            int row0 = (w * 16 + g) * 68, row1 = (w * 16 + g + 8) * 68;
            sH[row0 + nt * 8 + 2 * tig]     = f2tf32(fmaxf(c0, 0.0f));
            sH[row0 + nt * 8 + 2 * tig + 1] = f2tf32(fmaxf(c1, 0.0f));
            sH[row1 + nt * 8 + 2 * tig]     = f2tf32(fmaxf(c2, 0.0f));
            sH[row1 + nt * 8 + 2 * tig + 1] = f2tf32(fmaxf(c3, 0.0f));
        }
        __syncwarp();

        uint32_t hf[32];
        #pragma unroll
        for (int k = 0; k < 8; k++) {
            int row0 = (w * 16 + g) * 68, row1 = (w * 16 + g + 8) * 68;
            hf[k * 4 + 0] = sH[row0 + k * 8 + tig];
            hf[k * 4 + 1] = sH[row1 + k * 8 + tig];
            hf[k * 4 + 2] = sH[row0 + k * 8 + tig + 4];
            hf[k * 4 + 3] = sH[row1 + k * 8 + tig + 4];
        }

        #pragma unroll
        for (int nt = 0; nt < 2; nt++) {
            float c0 = sb2[nt * 8 + 2 * tig], c1 = sb2[nt * 8 + 2 * tig + 1];
            float c2 = c0, c3 = c1;
            #pragma unroll
            for (int k = 0; k < 8; k++) {
                uint32_t b0 = sW2B[(nt * 8 + k) * 64 + lane];
                uint32_t b1r = sW2B[(nt * 8 + k) * 64 + 32 + lane];
                mma_tf32(c0, c1, c2, c3,
                         hf[k * 4 + 0], hf[k * 4 + 1], hf[k * 4 + 2], hf[k * 4 + 3],
                         b0, b1r);
            }
            int col = nt * 8 + 2 * tig;
            int r0 = node0 + w * 16 + g;
            int r2 = r0 + 8;
            if (r0 < N_NODES)
                *reinterpret_cast<float2*>(&out[(size_t)r0 * 16 + col]) = make_float2(c0, c1);
            if (r2 < N_NODES)
                *reinterpret_cast<float2*>(&out[(size_t)r2 * 16 + col]) = make_float2(c2, c3);
        }
    }
}

// ---------------------------------------------------------------------------
extern "C" void kernel_launch(void* const* d_in, const int* in_sizes, int n_in,
                              void* d_out, int out_size) {
    const float* x   = (const float*)d_in[0];
    const int*   ei  = (const int*)d_in[1];   // int64 downcast to int32 by harness
    const float* eps = (const float*)d_in[2];
    const float* W1  = (const float*)d_in[3];
    const float* b1  = (const float*)d_in[4];
    const float* W2  = (const float*)d_in[5];
    const float* b2  = (const float*)d_in[6];
    float*       out = (float*)d_out;

    const int EB = (N_EDGES + 255) / 256;     // 6250

    k_count_conv<<<EB, 256>>>(ei, (const float4*)x);
    k_scan_lb<<<N_SCAN_BLOCKS, SCAN_BLK>>>();
    k_fill<<<EB, 256>>>(ei);

    {
        long long total = (long long)N_NODES * 8;
        int blocks = (int)((total + 255) / 256);
        k_gather_h<<<blocks, 256>>>((const float4*)x, eps);
    }

    {
        size_t shbytes = (size_t)(64 * 68 * 2 + 4096 + 1024) * 4 + (64 + 16) * 4;
        cudaFuncSetAttribute(k_mlp_tc,
                             cudaFuncAttributeMaxDynamicSharedMemorySize,
                             (int)shbytes);
        k_mlp_tc<<<MLP_GRID, 128, shbytes>>>(W1, b1, W2, b2, out);
    }
}

// round 15
// speedup vs baseline: 1.8835x; 1.0523x over previous
#include <cuda_runtime.h>
#include <cuda_fp16.h>
#include <cstdint>

#define N_NODES 100000
#define N_EDGES 1600000

#define SCAN_BLK 1024
#define N_SCAN_BLOCKS ((N_NODES + SCAN_BLK - 1) / SCAN_BLK)   // 98

#define FLAG_AGG (1ULL << 62)
#define FLAG_INC (2ULL << 62)

// Device-global scratch (no allocation allowed).
// g_count zero-initialized at load; re-zeroed by the scan after each use.
// g_pkt reset by k_count_conv each call (stream-ordered before the scan).
__device__ __align__(16) float  g_agg[N_NODES * 64];
__device__ __align__(16) __half g_xh[N_NODES * 64];
__device__ int g_count[N_NODES];
__device__ int g_off[N_NODES + 1];
__device__ int g_cursor[N_NODES];
__device__ int g_perm[N_EDGES];
__device__ unsigned long long g_pkt[N_SCAN_BLOCKS];

// ---------------------------------------------------------------------------
// Pass 1 (merged): dst histogram + x -> fp16 conversion + scan-state reset.
// ---------------------------------------------------------------------------
__global__ void k_count_conv(const int* __restrict__ ei,
                             const float4* __restrict__ x4) {
    int e = blockIdx.x * blockDim.x + threadIdx.x;
    if (blockIdx.x == 0 && threadIdx.x < N_SCAN_BLOCKS) g_pkt[threadIdx.x] = 0;
    if (e >= N_EDGES) return;

    float4 v = __ldg(x4 + e);
    __half2 h0 = __floats2half2_rn(v.x, v.y);
    __half2 h1 = __floats2half2_rn(v.z, v.w);
    uint2 pk;
    pk.x = *reinterpret_cast<uint32_t*>(&h0);
    pk.y = *reinterpret_cast<uint32_t*>(&h1);
    reinterpret_cast<uint2*>(g_xh)[e] = pk;

    int d = __ldg(ei + N_EDGES + e);
    if ((unsigned)d < N_NODES) atomicAdd(&g_count[d], 1);
}

// ---------------------------------------------------------------------------
// Pass 2: single-pass exclusive scan with decoupled lookback (98 blocks).
// ---------------------------------------------------------------------------
__global__ __launch_bounds__(SCAN_BLK) void k_scan_lb() {
    __shared__ int sdata[SCAN_BLK];
    __shared__ int s_exc;
    int tid = threadIdx.x, b = blockIdx.x;
    int i = b * SCAN_BLK + tid;
    int v = (i < N_NODES) ? g_count[i] : 0;
    sdata[tid] = v;
    __syncthreads();
    #pragma unroll
    for (int d = 1; d < SCAN_BLK; d <<= 1) {
        int t = (tid >= d) ? sdata[tid - d] : 0;
        __syncthreads();
        sdata[tid] += t;
        __syncthreads();
    }
    int incl = sdata[tid];
    int total = sdata[SCAN_BLK - 1];

    if (b == 0) {
        if (tid == 0) {
            s_exc = 0;
            atomicExch(&g_pkt[0], FLAG_INC | (unsigned long long)(unsigned)total);
        }
    } else {
        if (tid == 0)
            atomicExch(&g_pkt[b], FLAG_AGG | (unsigned long long)(unsigned)total);
        if (tid < 32) {
            int exc = 0;
            int look = b - 1;
            while (true) {
                int idx = look - 31 + tid;           // lane 31 reads 'look'
                unsigned long long p = 0;
                if (idx >= 0) {
                    do { p = atomicAdd(&g_pkt[idx], 0ULL); } while (p < FLAG_AGG);
                }
                int myval = (idx >= 0) ? (int)(p & 0xFFFFFFFFULL) : 0;
                unsigned incmask = __ballot_sync(0xFFFFFFFFu,
                                                 idx >= 0 && (p & FLAG_INC));
                if (incmask) {
                    int hi = 31 - __clz(incmask);    // closest INC predecessor
                    int c = (tid >= hi) ? myval : 0;
                    #pragma unroll
                    for (int o = 16; o; o >>= 1) c += __shfl_xor_sync(0xFFFFFFFFu, c, o);
                    exc += c;
                    break;
                } else {
                    int c = myval;
                    #pragma unroll
                    for (int o = 16; o; o >>= 1) c += __shfl_xor_sync(0xFFFFFFFFu, c, o);
                    exc += c;
                    look -= 32;
                }
            }
            if (tid == 0) {
                s_exc = exc;
                atomicExch(&g_pkt[b],
                           FLAG_INC | (unsigned long long)(unsigned)(exc + total));
            }
        }
    }
    __syncthreads();
    int exc = s_exc;

    if (i < N_NODES) {
        int off = exc + incl - v;
        g_off[i] = off;
        g_cursor[i] = off;
        g_count[i] = 0;
    }
    if (b == 0 && tid == 0) g_off[N_NODES] = N_EDGES;
}

// ---------------------------------------------------------------------------
// Pass 3: fill permutation: perm[pos] = src, grouped by dst
// ---------------------------------------------------------------------------
__global__ void k_fill(const int* __restrict__ ei) {
    int e = blockIdx.x * blockDim.x + threadIdx.x;
    if (e >= N_EDGES) return;
    int s = __ldg(ei + e);
    int d = __ldg(ei + N_EDGES + e);
    if ((unsigned)d >= N_NODES || (unsigned)s >= N_NODES) return;
    int pos = atomicAdd(&g_cursor[d], 1);
    g_perm[pos] = s;
}

// ---------------------------------------------------------------------------
// Pass 4: segment gather-sum over fp16 x + fp32 (1+eps)*x self-term.
// 8 threads/node, thread q owns one 16B chunk (4 half2).
// 4 edges per iteration: 4 loads in flight, then a 2-level HADD2 tree
// (12 HADD2) collapses them; one convert+FADD into fp32 accumulators.
// ---------------------------------------------------------------------------
__device__ __forceinline__ __half2 u2h(uint32_t u) {
    return *reinterpret_cast<__half2*>(&u);
}

__global__ __launch_bounds__(256) void k_gather_h(const float4* __restrict__ x4,
                                                  const float* __restrict__ eps) {
    int tid = blockIdx.x * blockDim.x + threadIdx.x;
    int node = tid >> 3;
    int q = tid & 7;
    if (node >= N_NODES) return;

    float s = 1.0f + __ldg(eps);
    float4 a0 = __ldg(x4 + (size_t)node * 16 + q * 2);
    float4 a1 = __ldg(x4 + (size_t)node * 16 + q * 2 + 1);
    float acc0 = a0.x * s, acc1 = a0.y * s, acc2 = a0.z * s, acc3 = a0.w * s;
    float acc4 = a1.x * s, acc5 = a1.y * s, acc6 = a1.z * s, acc7 = a1.w * s;

    const __half* xh = g_xh;
    int j   = __ldg(&g_off[node]);
    int end = __ldg(&g_off[node + 1]);

    for (; j + 4 <= end; j += 4) {
        int s0 = __ldg(&g_perm[j]);
        int s1 = __ldg(&g_perm[j + 1]);
        int s2 = __ldg(&g_perm[j + 2]);
        int s3 = __ldg(&g_perm[j + 3]);
        uint4 u0 = *reinterpret_cast<const uint4*>(xh + (size_t)s0 * 64 + q * 8);
        uint4 u1 = *reinterpret_cast<const uint4*>(xh + (size_t)s1 * 64 + q * 8);
        uint4 u2 = *reinterpret_cast<const uint4*>(xh + (size_t)s2 * 64 + q * 8);
        uint4 u3 = *reinterpret_cast<const uint4*>(xh + (size_t)s3 * 64 + q * 8);

        // level 1: pair sums (8 HADD2)
        __half2 p0 = __hadd2(u2h(u0.x), u2h(u1.x));
        __half2 p1 = __hadd2(u2h(u0.y), u2h(u1.y));
        __half2 p2 = __hadd2(u2h(u0.z), u2h(u1.z));
        __half2 p3 = __hadd2(u2h(u0.w), u2h(u1.w));
        __half2 r0 = __hadd2(u2h(u2.x), u2h(u3.x));
        __half2 r1 = __hadd2(u2h(u2.y), u2h(u3.y));
        __half2 r2 = __hadd2(u2h(u2.z), u2h(u3.z));
        __half2 r3 = __hadd2(u2h(u2.w), u2h(u3.w));
        // level 2: quad sums (4 HADD2)
        __half2 t0 = __hadd2(p0, r0);
        __half2 t1 = __hadd2(p1, r1);
        __half2 t2 = __hadd2(p2, r2);
        __half2 t3 = __hadd2(p3, r3);
        // convert once, accumulate fp32
        float2 f0 = __half22float2(t0);
        float2 f1 = __half22float2(t1);
        float2 f2 = __half22float2(t2);
        float2 f3 = __half22float2(t3);
        acc0 += f0.x; acc1 += f0.y; acc2 += f1.x; acc3 += f1.y;
        acc4 += f2.x; acc5 += f2.y; acc6 += f3.x; acc7 += f3.y;
    }
    for (; j < end; j++) {
        int s0 = __ldg(&g_perm[j]);
        uint4 u = *reinterpret_cast<const uint4*>(xh + (size_t)s0 * 64 + q * 8);
        float2 f;
        f = __half22float2(u2h(u.x)); acc0 += f.x; acc1 += f.y;
        f = __half22float2(u2h(u.y)); acc2 += f.x; acc3 += f.y;
        f = __half22float2(u2h(u.z)); acc4 += f.x; acc5 += f.y;
        f = __half22float2(u2h(u.w)); acc6 += f.x; acc7 += f.y;
    }

    float4* dst = reinterpret_cast<float4*>(g_agg) + (size_t)node * 16 + q * 2;
    dst[0] = make_float4(acc0, acc1, acc2, acc3);
    dst[1] = make_float4(acc4, acc5, acc6, acc7);
}

// ---------------------------------------------------------------------------
// Pass 5: out = relu(agg @ W1 + b1) @ W2 + b2 via tf32 mma.sync.m16n8k8.
// ---------------------------------------------------------------------------
#define N_TILES ((N_NODES + 63) / 64)      // 1563
#define MLP_GRID (148 * 4)

__device__ __forceinline__ uint32_t f2tf32(float v) {
    uint32_t r;
    asm("cvt.rna.tf32.f32 %0, %1;" : "=r"(r) : "f"(v));
    return r;
}

__device__ __forceinline__ void mma_tf32(float& c0, float& c1, float& c2, float& c3,
                                         uint32_t a0, uint32_t a1, uint32_t a2, uint32_t a3,
                                         uint32_t b0, uint32_t b1) {
    asm volatile(
        "mma.sync.aligned.m16n8k8.row.col.f32.tf32.tf32.f32 "
        "{%0,%1,%2,%3}, {%4,%5,%6,%7}, {%8,%9}, {%0,%1,%2,%3};"
        : "+f"(c0), "+f"(c1), "+f"(c2), "+f"(c3)
        : "r"(a0), "r"(a1), "r"(a2), "r"(a3), "r"(b0), "r"(b1));
}

extern __shared__ float smlp[];

__global__ __launch_bounds__(128) void k_mlp_tc(const float* __restrict__ W1,
                                                const float* __restrict__ b1,
                                                const float* __restrict__ W2,
                                                const float* __restrict__ b2,
                                                float* __restrict__ out) {
    uint32_t* sA   = (uint32_t*)smlp;              // [64][68] tf32 bits
    uint32_t* sH   = sA + 64 * 68;                 // [64][68] tf32 bits
    uint32_t* sW1B = sH + 64 * 68;                 // 4096
    uint32_t* sW2B = sW1B + 4096;                  // 1024
    float*    sb1  = (float*)(sW2B + 1024);        // [64]
    float*    sb2  = sb1 + 64;                     // [16]

    int t = threadIdx.x;
    int lane = t & 31, w = t >> 5;
    int g = lane >> 2, tig = lane & 3;

    for (int i = t; i < 4096; i += 128) {
        int l = i & 31, half = (i >> 5) & 1, kk = (i >> 6) & 7, nt = i >> 9;
        int gg = l >> 2, tt = l & 3;
        sW1B[i] = f2tf32(W1[(kk * 8 + tt + half * 4) * 64 + nt * 8 + gg]);
    }
    for (int i = t; i < 1024; i += 128) {
        int l = i & 31, half = (i >> 5) & 1, kk = (i >> 6) & 7, nt = i >> 9;
        int gg = l >> 2, tt = l & 3;
        sW2B[i] = f2tf32(W2[(kk * 8 + tt + half * 4) * 16 + nt * 8 + gg]);
    }
    if (t < 64) sb1[t] = b1[t];
    if (t < 16) sb2[t] = b2[t];

    for (int tile = blockIdx.x; tile < N_TILES; tile += gridDim.x) {
        int node0 = tile * 64;
        int nrows = N_NODES - node0; if (nrows > 64) nrows = 64;

        __syncthreads();
        for (int i = t; i < 1024; i += 128) {
            int r = i >> 4, c4 = (i & 15) * 4;
            float4 v = (r < nrows)
                ? *reinterpret_cast<const float4*>(&g_agg[(size_t)(node0 + r) * 64 + c4])
                : make_float4(0.f, 0.f, 0.f, 0.f);
            uint32_t* dst = &sA[r * 68 + c4];
            dst[0] = f2tf32(v.x); dst[1] = f2tf32(v.y);
            dst[2] = f2tf32(v.z); dst[3] = f2tf32(v.w);
        }
        __syncthreads();

        uint32_t af[32];
        #pragma unroll
        for (int k = 0; k < 8; k++) {
            int row0 = (w * 16 + g) * 68, row1 = (w * 16 + g + 8) * 68;
            af[k * 4 + 0] = sA[row0 + k * 8 + tig];
            af[k * 4 + 1] = sA[row1 + k * 8 + tig];
            af[k * 4 + 2] = sA[row0 + k * 8 + tig + 4];
            af[k * 4 + 3] = sA[row1 + k * 8 + tig + 4];
        }

        #pragma unroll
        for (int nt = 0; nt < 8; nt++) {
            float c0 = sb1[nt * 8 + 2 * tig], c1 = sb1[nt * 8 + 2 * tig + 1];
            float c2 = c0, c3 = c1;
            #pragma unroll
            for (int k = 0; k < 8; k++) {
                uint32_t b0 = sW1B[(nt * 8 + k) * 64 + lane];
                uint32_t b1r = sW1B[(nt * 8 + k) * 64 + 32 + lane];
                mma_tf32(c0, c1, c2, c3,
                         af[k * 4 + 0], af[k * 4 + 1], af[k * 4 + 2], af[k * 4 + 3],
                         b0, b1r);
            }
            int row0 = (w * 16 + g) * 68, row1 = (w * 16 + g + 8) * 68;
            sH[row0 + nt * 8 + 2 * tig]     = f2tf32(fmaxf(c0, 0.0f));
            sH[row0 + nt * 8 + 2 * tig + 1] = f2tf32(fmaxf(c1, 0.0f));
            sH[row1 + nt * 8 + 2 * tig]     = f2tf32(fmaxf(c2, 0.0f));
            sH[row1 + nt * 8 + 2 * tig + 1] = f2tf32(fmaxf(c3, 0.0f));
        }
        __syncwarp();

        uint32_t hf[32];
        #pragma unroll
        for (int k = 0; k < 8; k++) {
            int row0 = (w * 16 + g) * 68, row1 = (w * 16 + g + 8) * 68;
            hf[k * 4 + 0] = sH[row0 + k * 8 + tig];
            hf[k * 4 + 1] = sH[row1 + k * 8 + tig];
            hf[k * 4 + 2] = sH[row0 + k * 8 + tig + 4];
            hf[k * 4 + 3] = sH[row1 + k * 8 + tig + 4];
        }

        #pragma unroll
        for (int nt = 0; nt < 2; nt++) {
            float c0 = sb2[nt * 8 + 2 * tig], c1 = sb2[nt * 8 + 2 * tig + 1];
            float c2 = c0, c3 = c1;
            #pragma unroll
            for (int k = 0; k < 8; k++) {
                uint32_t b0 = sW2B[(nt * 8 + k) * 64 + lane];
                uint32_t b1r = sW2B[(nt * 8 + k) * 64 + 32 + lane];
                mma_tf32(c0, c1, c2, c3,
                         hf[k * 4 + 0], hf[k * 4 + 1], hf[k * 4 + 2], hf[k * 4 + 3],
                         b0, b1r);
            }
            int col = nt * 8 + 2 * tig;
            int r0 = node0 + w * 16 + g;
            int r2 = r0 + 8;
            if (r0 < N_NODES)
                *reinterpret_cast<float2*>(&out[(size_t)r0 * 16 + col]) = make_float2(c0, c1);
            if (r2 < N_NODES)
                *reinterpret_cast<float2*>(&out[(size_t)r2 * 16 + col]) = make_float2(c2, c3);
        }
    }
}

// ---------------------------------------------------------------------------
extern "C" void kernel_launch(void* const* d_in, const int* in_sizes, int n_in,
                              void* d_out, int out_size) {
    const float* x   = (const float*)d_in[0];
    const int*   ei  = (const int*)d_in[1];   // int64 downcast to int32 by harness
    const float* eps = (const float*)d_in[2];
    const float* W1  = (const float*)d_in[3];
    const float* b1  = (const float*)d_in[4];
    const float* W2  = (const float*)d_in[5];
    const float* b2  = (const float*)d_in[6];
    float*       out = (float*)d_out;

    const int EB = (N_EDGES + 255) / 256;     // 6250

    k_count_conv<<<EB, 256>>>(ei, (const float4*)x);
    k_scan_lb<<<N_SCAN_BLOCKS, SCAN_BLK>>>();
    k_fill<<<EB, 256>>>(ei);

    {
        long long total = (long long)N_NODES * 8;
        int blocks = (int)((total + 255) / 256);
        k_gather_h<<<blocks, 256>>>((const float4*)x, eps);
    }

    {
        size_t shbytes = (size_t)(64 * 68 * 2 + 4096 + 1024) * 4 + (64 + 16) * 4;
        cudaFuncSetAttribute(k_mlp_tc,
                             cudaFuncAttributeMaxDynamicSharedMemorySize,
                             (int)shbytes);
        k_mlp_tc<<<MLP_GRID, 128, shbytes>>>(W1, b1, W2, b2, out);
    }
}